// round 6
// baseline (speedup 1.0000x reference)
#include <cuda_runtime.h>
#include <math.h>

#define PI_F 3.14159265358979323846f
#define BB 4
#define NJ 9216
#define TJ 1024
#define WPB 8   // warps (points) per block

// SoA context data, preprocessed once per launch.
// g_P1 = (y, x, r_bound, angle)   (invalid point -> y = 1e9, so d2 gates prune it)
// g_P2 = (cos a, sin a, 1/hw, 1/hl)   with hw = 0.5*w, hl = 0.5*l
__device__ float4 g_P1[BB * NJ];
__device__ float4 g_P2[BB * NJ];

__device__ __forceinline__ float pow10f(float x) {
    float x2 = x * x;
    float x4 = x2 * x2;
    float x8 = x4 * x4;
    return x8 * x2;
}

// t^(-0.1) via MUFU lg2/ex2 (forced via PTX so it never falls back to libm)
__device__ __forceinline__ float powm01f(float t) {
    float l, r;
    asm("lg2.approx.f32 %0, %1;" : "=f"(l) : "f"(t));
    l = -0.1f * l;
    asm("ex2.approx.f32 %0, %1;" : "=f"(r) : "f"(l));
    return r;
}

__global__ void prep_kernel(const float* __restrict__ cc, const int* __restrict__ mask) {
    int idx = blockIdx.x * blockDim.x + threadIdx.x;
    if (idx >= BB * NJ) return;
    const float* p = cc + (long)idx * 5;
    bool valid = (mask[idx] != 0);   // nonzero word: works for int32 {0,1} and float32 {0.,1.}
    float y  = fminf(fmaxf(p[0], 0.f), 256.f);
    float x  = fminf(fmaxf(p[1], 0.f), 256.f);
    float wv = fminf(fmaxf(p[2], 2.f), 32.f);
    float lv = fminf(fmaxf(p[3], 2.f), 32.f);
    float a  = p[4];
    a = a - floorf(a / PI_F) * PI_F;          // jnp.mod(a, pi)
    float sa, ca;
    sincosf(a, &sa, &ca);
    float hw = 0.5f * wv, hl = 0.5f * lv;
    // superellipse p=10 radius bound: r <= 2^(1/2 - 1/10) * max(hw,hl)
    float rb = 1.3195080f * fmaxf(hw, hl) + 1e-3f;
    g_P1[idx] = valid ? make_float4(y, x, rb, a) : make_float4(1e9f, 1e9f, 0.f, 0.f);
    g_P2[idx] = make_float4(ca, sa, 1.f / hw, 1.f / hl);
}

__device__ __forceinline__ float bilin(const float* __restrict__ img, float y, float x) {
    float yc = fminf(fmaxf(y, 0.f), 255.f);
    float xc = fminf(fmaxf(x, 0.f), 255.f);
    float y0 = floorf(yc), x0 = floorf(xc);
    int iy0 = (int)y0, ix0 = (int)x0;
    int iy1 = min(iy0 + 1, 255), ix1 = min(ix0 + 1, 255);
    float wy = yc - y0, wx = xc - x0;
    float v00 = img[iy0 * 256 + ix0];
    float v01 = img[iy0 * 256 + ix1];
    float v10 = img[iy1 * 256 + ix0];
    float v11 = img[iy1 * 256 + ix1];
    return v00 * (1.f - wy) * (1.f - wx) + v01 * (1.f - wy) * wx
         + v10 * wy * (1.f - wx) + v11 * wy * wx;
}

__device__ __forceinline__ float trilin(const float* __restrict__ m3, float y, float x,
                                        float m, float vmin, float vmax, bool cyclic) {
    float c = (m - vmin) / (vmax - vmin) * 32.f - 0.5f;
    int i0, i1; float cw;
    if (cyclic) {
        c = c - floorf(c * (1.f / 32.f)) * 32.f;   // mod 32
        float c0 = floorf(c);
        cw = c - c0;
        i0 = ((int)c0) & 31;
        i1 = (i0 + 1) & 31;
    } else {
        c = fminf(fmaxf(c, 0.f), 31.f);
        float c0 = floorf(c);
        cw = c - c0;
        i0 = (int)c0;
        i1 = min(i0 + 1, 31);
    }
    return (1.f - cw) * bilin(m3 + i0 * 65536, y, x) + cw * bilin(m3 + i1 * 65536, y, x);
}

__global__ __launch_bounds__(256) void pair_kernel(
    const float* __restrict__ cc,
    const float* __restrict__ pem, const float* __restrict__ mwm,
    const float* __restrict__ mlm, const float* __restrict__ mam,
    const float* __restrict__ comb_w, const float* __restrict__ comb_b,
    float* __restrict__ out, int P, int out_size)
{
    __shared__ float4 sP1[TJ];
    __shared__ float4 sP2[TJ];

    const int bpb  = P / WPB;
    const int b    = blockIdx.x / bpb;
    const int i    = (blockIdx.x % bpb) * WPB + (threadIdx.x >> 5);
    const int lane = threadIdx.x & 31;
    const int gi   = b * NJ + i;

    float4 p1 = g_P1[gi];
    float4 p2 = g_P2[gi];
    const bool  pmv = (p1.x < 1e8f);
    const float yi = p1.x, xi = p1.y, rib = p1.z, ai = p1.w;
    const float cai = p2.x, sai = p2.y, ihw = p2.z, ihl = p2.w;

    float omax = 0.f;   // overlap contributions are >= 0; self/invalid give 0
    float amin = 0.f;   // align matrix always contains 0 entries (self pair)

    for (int tile = 0; tile < NJ; tile += TJ) {
        __syncthreads();
        const float4* __restrict__ g1 = g_P1 + b * NJ + tile;
        const float4* __restrict__ g2 = g_P2 + b * NJ + tile;
        for (int t = threadIdx.x; t < TJ; t += 256) {
            sP1[t] = g1[t];
            sP2[t] = g2[t];
        }
        __syncthreads();
        if (!pmv) continue;   // per-warp uniform; all threads still hit barriers

        #pragma unroll 4
        for (int s = lane; s < TJ; s += 32) {
            float4 q = sP1[s];
            float dy = yi - q.x;
            float dx = xi - q.y;
            float d2 = fmaf(dy, dy, dx * dx);
            if (d2 <= 0.f) continue;                 // nonself (also prunes invalid j)
            float rsum = rib + q.z;
            bool doOv = d2 < rsum * rsum;            // overlap > 0 possible only here
            bool doAl = d2 < 1024.f;                 // dist < 32 (strict)
            if (!(doOv || doAl)) continue;

            if (doOv) {
                float d2c  = fmaxf(d2, 1e-12f);
                float rinv = rsqrtf(d2c);
                float dist = d2c * rinv;
                float ct = dy * rinv;                // cos(theta)
                float st = dx * rinv;                // sin(theta)
                // cos/sin(theta - a) via angle-difference identity (no atan2)
                float ci = fabsf(fmaf(ct, cai,  st * sai)) + 1e-8f;
                float si = fabsf(fmaf(st, cai, -(ct * sai))) + 1e-8f;
                float4 c2 = sP2[s];
                float cj = fabsf(fmaf(ct, c2.x,  st * c2.y)) + 1e-8f;
                float sj = fabsf(fmaf(st, c2.x, -(ct * c2.y))) + 1e-8f;
                float ti = pow10f(ci * ihw)  + pow10f(si * ihl);
                float tj = pow10f(cj * c2.z) + pow10f(sj * c2.w);
                float ri = powm01f(ti);
                float rj = powm01f(tj);
                float ov = 1.f - __fdividef(dist, ri + rj + 1e-8f);
                ov = fminf(fmaxf(ov, 0.f), 1.f);
                omax = fmaxf(omax, ov);
            }
            if (doAl) {
                float ad = ai - q.w;                 // both in [0, pi)
                if (ad < 0.f) ad += PI_F;            // mod pi
                ad = fminf(ad, PI_F - ad);
                float al = fminf(fmaxf(fmaf(ad, 4.f / PI_F, -1.f), -1.f), 1.f);
                amin = fminf(amin, al);
            }
        }
    }

    // warp reductions (one warp == one point)
    #pragma unroll
    for (int off = 16; off; off >>= 1) {
        omax = fmaxf(omax, __shfl_xor_sync(0xffffffffu, omax, off));
        amin = fminf(amin, __shfl_xor_sync(0xffffffffu, amin, off));
    }

    if (lane == 0) {
        int oidx = b * P + i;
        if (oidx < out_size) {
            float e = 0.f;
            if (pmv) {
                const float* pr = cc + (long)gi * 5;
                float y  = fminf(fmaxf(pr[0], 0.f), 256.f);
                float x  = fminf(fmaxf(pr[1], 0.f), 256.f);
                float wv = fminf(fmaxf(pr[2], 2.f), 32.f);
                float lv = fminf(fmaxf(pr[3], 2.f), 32.f);
                float a  = pr[4];
                a = a - floorf(a / PI_F) * PI_F;
                float pos  = bilin(pem, y, x);
                float wen  = trilin(mwm, y, x, wv, 2.f, 32.f, false);
                float len  = trilin(mlm, y, x, lv, 2.f, 32.f, false);
                float aen  = trilin(mam, y, x, a,  0.f, PI_F, true);
                float area = 1.f - 2.f * fminf(fmaxf(wv * lv * (1.f / 256.f), 0.f), 1.f);
                e = pos  * comb_w[0] + wen  * comb_w[1] + len  * comb_w[2]
                  + aen  * comb_w[3] + omax * comb_w[4] + amin * comb_w[5]
                  + area * comb_w[6] + comb_b[0];
            }
            out[oidx] = e;
        }
    }
}

__global__ void reduce_kernel(const float* __restrict__ en, float* __restrict__ outp, int P) {
    __shared__ double sh[256];
    double tot = 0.0;
    for (int b = 0; b < BB; b++) {
        double s = 0.0;
        for (int t = threadIdx.x; t < P; t += 256) s += (double)en[b * P + t];
        sh[threadIdx.x] = s;
        __syncthreads();
        for (int off = 128; off; off >>= 1) {
            if (threadIdx.x < off) sh[threadIdx.x] += sh[threadIdx.x + off];
            __syncthreads();
        }
        if (threadIdx.x == 0) {
            outp[b] = (float)sh[0];
            tot += sh[0];
        }
        __syncthreads();
    }
    if (threadIdx.x == 0) outp[BB] = (float)tot;
}

extern "C" void kernel_launch(void* const* d_in, const int* in_sizes, int n_in,
                              void* d_out, int out_size) {
    const float* cc  = (const float*)d_in[0];
    const int*   msk = (const int*)  d_in[1];
    const float* pem = (const float*)d_in[2];
    const float* mwm = (const float*)d_in[3];
    const float* mlm = (const float*)d_in[4];
    const float* mam = (const float*)d_in[5];
    const float* cwv = (const float*)d_in[6];
    const float* cbv = (const float*)d_in[7];
    float* out = (float*)d_out;

    // compute_context=0 -> P=1024 points/batch (out: 4096 energies + 4 per_subset + 1 total).
    // If out_size indicates the context path (pts == full 9N), use P=9216.
    int P = (out_size >= BB * NJ) ? NJ : 1024;

    prep_kernel<<<(BB * NJ + 255) / 256, 256>>>(cc, msk);
    pair_kernel<<<BB * (P / WPB), 256>>>(cc, pem, mwm, mlm, mam, cwv, cbv, out, P, out_size);
    if (out_size >= BB * P + BB + 1)
        reduce_kernel<<<1, 256>>>(out, out + BB * P, P);
}

// round 7
// speedup vs baseline: 1.5480x; 1.5480x over previous
#include <cuda_runtime.h>
#include <math.h>

#define PI_F 3.14159265358979323846f
#define BB 4
#define NJ 9216
#define TJ 1024
#define WPB 8    // warps (points) per block
#define QCAP 64  // per-warp hit stack (max residual 31 + 32 new pushes)

// SoA context data, preprocessed once per launch.
// g_P1 = (y, x, r_bound, angle)   (invalid point -> y = 1e9, so d2 gates prune it)
// g_P2 = (cos a, sin a, 1/hw, 1/hl)   with hw = 0.5*w, hl = 0.5*l
__device__ float4 g_P1[BB * NJ];
__device__ float4 g_P2[BB * NJ];

__device__ __forceinline__ float pow10f(float x) {
    float x2 = x * x;
    float x4 = x2 * x2;
    float x8 = x4 * x4;
    return x8 * x2;
}

// t^(-0.1) via MUFU lg2/ex2 (forced via PTX so it never falls back to libm)
__device__ __forceinline__ float powm01f(float t) {
    float l, r;
    asm("lg2.approx.f32 %0, %1;" : "=f"(l) : "f"(t));
    l = -0.1f * l;
    asm("ex2.approx.f32 %0, %1;" : "=f"(r) : "f"(l));
    return r;
}

__global__ void prep_kernel(const float* __restrict__ cc, const int* __restrict__ mask) {
    int idx = blockIdx.x * blockDim.x + threadIdx.x;
    if (idx >= BB * NJ) return;
    const float* p = cc + (long)idx * 5;
    bool valid = (mask[idx] != 0);
    float y  = fminf(fmaxf(p[0], 0.f), 256.f);
    float x  = fminf(fmaxf(p[1], 0.f), 256.f);
    float wv = fminf(fmaxf(p[2], 2.f), 32.f);
    float lv = fminf(fmaxf(p[3], 2.f), 32.f);
    float a  = p[4];
    a = a - floorf(a / PI_F) * PI_F;          // jnp.mod(a, pi)
    float sa, ca;
    sincosf(a, &sa, &ca);
    float hw = 0.5f * wv, hl = 0.5f * lv;
    // superellipse p=10 radius bound: r <= 2^(1/2 - 1/10) * max(hw,hl)
    float rb = 1.3195080f * fmaxf(hw, hl) + 1e-3f;
    g_P1[idx] = valid ? make_float4(y, x, rb, a) : make_float4(1e9f, 1e9f, 0.f, 0.f);
    g_P2[idx] = make_float4(ca, sa, 1.f / hw, 1.f / hl);
}

__device__ __forceinline__ float bilin(const float* __restrict__ img, float y, float x) {
    float yc = fminf(fmaxf(y, 0.f), 255.f);
    float xc = fminf(fmaxf(x, 0.f), 255.f);
    float y0 = floorf(yc), x0 = floorf(xc);
    int iy0 = (int)y0, ix0 = (int)x0;
    int iy1 = min(iy0 + 1, 255), ix1 = min(ix0 + 1, 255);
    float wy = yc - y0, wx = xc - x0;
    float v00 = img[iy0 * 256 + ix0];
    float v01 = img[iy0 * 256 + ix1];
    float v10 = img[iy1 * 256 + ix0];
    float v11 = img[iy1 * 256 + ix1];
    return v00 * (1.f - wy) * (1.f - wx) + v01 * (1.f - wy) * wx
         + v10 * wy * (1.f - wx) + v11 * wy * wx;
}

__device__ __forceinline__ float trilin(const float* __restrict__ m3, float y, float x,
                                        float m, float vmin, float vmax, bool cyclic) {
    float c = (m - vmin) / (vmax - vmin) * 32.f - 0.5f;
    int i0, i1; float cw;
    if (cyclic) {
        c = c - floorf(c * (1.f / 32.f)) * 32.f;   // mod 32
        float c0 = floorf(c);
        cw = c - c0;
        i0 = ((int)c0) & 31;
        i1 = (i0 + 1) & 31;
    } else {
        c = fminf(fmaxf(c, 0.f), 31.f);
        float c0 = floorf(c);
        cw = c - c0;
        i0 = (int)c0;
        i1 = min(i0 + 1, 31);
    }
    return (1.f - cw) * bilin(m3 + i0 * 65536, y, x) + cw * bilin(m3 + i1 * 65536, y, x);
}

__global__ __launch_bounds__(256) void pair_kernel(
    const float* __restrict__ cc,
    const float* __restrict__ pem, const float* __restrict__ mwm,
    const float* __restrict__ mlm, const float* __restrict__ mam,
    const float* __restrict__ comb_w, const float* __restrict__ comb_b,
    float* __restrict__ out, int P, int out_size)
{
    __shared__ float4 sP1[TJ];
    __shared__ float4 sP2[TJ];
    __shared__ int    sQ[WPB][QCAP];

    const int bpb  = P / WPB;
    const int b    = blockIdx.x / bpb;
    const int wid  = threadIdx.x >> 5;
    const int i    = (blockIdx.x % bpb) * WPB + wid;
    const int lane = threadIdx.x & 31;
    const unsigned laneLT = (1u << lane) - 1u;
    const int gi   = b * NJ + i;

    float4 p1 = g_P1[gi];
    float4 p2 = g_P2[gi];
    const bool  pmv = (p1.x < 1e8f);
    const float yi = p1.x, xi = p1.y, rib = p1.z, ai = p1.w;
    const float cai = p2.x, sai = p2.y, ihw = p2.z, ihl = p2.w;

    float omax = 0.f;   // overlap contributions are >= 0; self/invalid give 0
    float amin = 0.f;   // align matrix always contains 0 entries (self pair)
    int   qn   = 0;     // per-warp hit-stack depth (uniform across warp)

    for (int tile = 0; tile < NJ; tile += TJ) {
        __syncthreads();
        const float4* __restrict__ g1 = g_P1 + b * NJ + tile;
        const float4* __restrict__ g2 = g_P2 + b * NJ + tile;
        for (int t = threadIdx.x; t < TJ; t += 256) {
            sP1[t] = g1[t];
            sP2[t] = g2[t];
        }
        __syncthreads();

        if (pmv) {   // warp-uniform; barriers are outside this branch
            #pragma unroll 2
            for (int s = lane; s < TJ; s += 32) {
                float4 q = sP1[s];
                float dy = yi - q.x;
                float dx = xi - q.y;
                float d2 = fmaf(dy, dy, dx * dx);
                bool nonself = (d2 > 0.f);           // also prunes invalid j (y=1e9)
                float rsum = rib + q.z;
                bool doOv = nonself && (d2 < rsum * rsum);
                bool doAl = nonself && (d2 < 1024.f);   // dist < 32 (strict)

                // align: cheap, predicated inline
                if (doAl) {
                    float ad = ai - q.w;             // both in [0, pi)
                    if (ad < 0.f) ad += PI_F;        // mod pi
                    ad = fminf(ad, PI_F - ad);
                    float al = fminf(fmaxf(fmaf(ad, 4.f / PI_F, -1.f), -1.f), 1.f);
                    amin = fminf(amin, al);
                }

                // overlap: push hit index, process densely when 32 are queued
                unsigned m = __ballot_sync(0xffffffffu, doOv);
                if (doOv) sQ[wid][qn + __popc(m & laneLT)] = s;
                qn += __popc(m);
                if (qn >= 32) {
                    qn -= 32;
                    int ss = sQ[wid][qn + lane];
                    float4 h1 = sP1[ss];
                    float4 h2 = sP2[ss];
                    float hdy = yi - h1.x;
                    float hdx = xi - h1.y;
                    float hd2 = fmaxf(fmaf(hdy, hdy, hdx * hdx), 1e-12f);
                    float rinv = rsqrtf(hd2);
                    float dist = hd2 * rinv;
                    float ct = hdy * rinv;           // cos(theta)
                    float st = hdx * rinv;           // sin(theta)
                    float ci = fabsf(fmaf(ct, cai,  st * sai)) + 1e-8f;
                    float si = fabsf(fmaf(st, cai, -(ct * sai))) + 1e-8f;
                    float cj = fabsf(fmaf(ct, h2.x,  st * h2.y)) + 1e-8f;
                    float sj = fabsf(fmaf(st, h2.x, -(ct * h2.y))) + 1e-8f;
                    float ti = pow10f(ci * ihw)  + pow10f(si * ihl);
                    float tj = pow10f(cj * h2.z) + pow10f(sj * h2.w);
                    float ri = powm01f(ti);
                    float rj = powm01f(tj);
                    float ov = 1.f - __fdividef(dist, ri + rj + 1e-8f);
                    omax = fmaxf(omax, fminf(fmaxf(ov, 0.f), 1.f));
                }
            }
            // tile-end drain (indices reference this tile's shared arrays)
            if (lane < qn) {
                int ss = sQ[wid][lane];
                float4 h1 = sP1[ss];
                float4 h2 = sP2[ss];
                float hdy = yi - h1.x;
                float hdx = xi - h1.y;
                float hd2 = fmaxf(fmaf(hdy, hdy, hdx * hdx), 1e-12f);
                float rinv = rsqrtf(hd2);
                float dist = hd2 * rinv;
                float ct = hdy * rinv;
                float st = hdx * rinv;
                float ci = fabsf(fmaf(ct, cai,  st * sai)) + 1e-8f;
                float si = fabsf(fmaf(st, cai, -(ct * sai))) + 1e-8f;
                float cj = fabsf(fmaf(ct, h2.x,  st * h2.y)) + 1e-8f;
                float sj = fabsf(fmaf(st, h2.x, -(ct * h2.y))) + 1e-8f;
                float ti = pow10f(ci * ihw)  + pow10f(si * ihl);
                float tj = pow10f(cj * h2.z) + pow10f(sj * h2.w);
                float ri = powm01f(ti);
                float rj = powm01f(tj);
                float ov = 1.f - __fdividef(dist, ri + rj + 1e-8f);
                omax = fmaxf(omax, fminf(fmaxf(ov, 0.f), 1.f));
            }
            qn = 0;
        }
    }

    // warp reductions (one warp == one point)
    #pragma unroll
    for (int off = 16; off; off >>= 1) {
        omax = fmaxf(omax, __shfl_xor_sync(0xffffffffu, omax, off));
        amin = fminf(amin, __shfl_xor_sync(0xffffffffu, amin, off));
    }

    if (lane == 0) {
        int oidx = b * P + i;
        if (oidx < out_size) {
            float e = 0.f;
            if (pmv) {
                const float* pr = cc + (long)gi * 5;
                float y  = fminf(fmaxf(pr[0], 0.f), 256.f);
                float x  = fminf(fmaxf(pr[1], 0.f), 256.f);
                float wv = fminf(fmaxf(pr[2], 2.f), 32.f);
                float lv = fminf(fmaxf(pr[3], 2.f), 32.f);
                float a  = pr[4];
                a = a - floorf(a / PI_F) * PI_F;
                float pos  = bilin(pem, y, x);
                float wen  = trilin(mwm, y, x, wv, 2.f, 32.f, false);
                float len  = trilin(mlm, y, x, lv, 2.f, 32.f, false);
                float aen  = trilin(mam, y, x, a,  0.f, PI_F, true);
                float area = 1.f - 2.f * fminf(fmaxf(wv * lv * (1.f / 256.f), 0.f), 1.f);
                e = pos  * comb_w[0] + wen  * comb_w[1] + len  * comb_w[2]
                  + aen  * comb_w[3] + omax * comb_w[4] + amin * comb_w[5]
                  + area * comb_w[6] + comb_b[0];
            }
            out[oidx] = e;
        }
    }
}

__global__ void reduce_kernel(const float* __restrict__ en, float* __restrict__ outp, int P) {
    __shared__ double sh[256];
    double tot = 0.0;
    for (int b = 0; b < BB; b++) {
        double s = 0.0;
        for (int t = threadIdx.x; t < P; t += 256) s += (double)en[b * P + t];
        sh[threadIdx.x] = s;
        __syncthreads();
        for (int off = 128; off; off >>= 1) {
            if (threadIdx.x < off) sh[threadIdx.x] += sh[threadIdx.x + off];
            __syncthreads();
        }
        if (threadIdx.x == 0) {
            outp[b] = (float)sh[0];
            tot += sh[0];
        }
        __syncthreads();
    }
    if (threadIdx.x == 0) outp[BB] = (float)tot;
}

extern "C" void kernel_launch(void* const* d_in, const int* in_sizes, int n_in,
                              void* d_out, int out_size) {
    const float* cc  = (const float*)d_in[0];
    const int*   msk = (const int*)  d_in[1];
    const float* pem = (const float*)d_in[2];
    const float* mwm = (const float*)d_in[3];
    const float* mlm = (const float*)d_in[4];
    const float* mam = (const float*)d_in[5];
    const float* cwv = (const float*)d_in[6];
    const float* cbv = (const float*)d_in[7];
    float* out = (float*)d_out;

    // compute_context=0 -> P=1024 points/batch (out: 4096 energies + 4 per_subset + 1 total).
    // If out_size indicates the context path (pts == full 9N), use P=9216.
    int P = (out_size >= BB * NJ) ? NJ : 1024;

    prep_kernel<<<(BB * NJ + 255) / 256, 256>>>(cc, msk);
    pair_kernel<<<BB * (P / WPB), 256>>>(cc, pem, mwm, mlm, mam, cwv, cbv, out, P, out_size);
    if (out_size >= BB * P + BB + 1)
        reduce_kernel<<<1, 256>>>(out, out + BB * P, P);
}

// round 8
// speedup vs baseline: 1.9113x; 1.2347x over previous
#include <cuda_runtime.h>
#include <math.h>

#define PI_F 3.14159265358979323846f
#define BB 4
#define NJ 9216
#define TJ 1024
#define WPB 8    // warps (points) per block
#define QCAP 64  // per-warp candidate stack (max residual 31 + 32 new pushes)
#define RBMAX 21.12f   // global bound on rb = 1.3195*max(hw,hl)+1e-3, hw,hl<=16

// SoA context data, preprocessed once per launch.
// g_YX = (y, x)            invalid point -> (1e9, 1e9) so the d2 gate prunes it
// g_RA = (r_bound, angle)
// g_P2 = (cos a, sin a, 1/hw, 1/hl)   with hw = 0.5*w, hl = 0.5*l
__device__ float2 g_YX[BB * NJ];
__device__ float2 g_RA[BB * NJ];
__device__ float4 g_P2[BB * NJ];

__device__ __forceinline__ float pow10f(float x) {
    float x2 = x * x;
    float x4 = x2 * x2;
    float x8 = x4 * x4;
    return x8 * x2;
}

// t^(-0.1) via MUFU lg2/ex2
__device__ __forceinline__ float powm01f(float t) {
    float l, r;
    asm("lg2.approx.f32 %0, %1;" : "=f"(l) : "f"(t));
    l = -0.1f * l;
    asm("ex2.approx.f32 %0, %1;" : "=f"(r) : "f"(l));
    return r;
}

__global__ void prep_kernel(const float* __restrict__ cc, const int* __restrict__ mask) {
    int idx = blockIdx.x * blockDim.x + threadIdx.x;
    if (idx >= BB * NJ) return;
    const float* p = cc + (long)idx * 5;
    bool valid = (mask[idx] != 0);
    float y  = fminf(fmaxf(p[0], 0.f), 256.f);
    float x  = fminf(fmaxf(p[1], 0.f), 256.f);
    float wv = fminf(fmaxf(p[2], 2.f), 32.f);
    float lv = fminf(fmaxf(p[3], 2.f), 32.f);
    float a  = p[4];
    a = a - floorf(a / PI_F) * PI_F;          // jnp.mod(a, pi)
    float sa, ca;
    sincosf(a, &sa, &ca);
    float hw = 0.5f * wv, hl = 0.5f * lv;
    // superellipse p=10 radius bound: r <= 2^(1/2 - 1/10) * max(hw,hl)
    float rb = 1.3195080f * fmaxf(hw, hl) + 1e-3f;
    g_YX[idx] = valid ? make_float2(y, x) : make_float2(1e9f, 1e9f);
    g_RA[idx] = make_float2(rb, a);
    g_P2[idx] = make_float4(ca, sa, 1.f / hw, 1.f / hl);
}

__device__ __forceinline__ float bilin(const float* __restrict__ img, float y, float x) {
    float yc = fminf(fmaxf(y, 0.f), 255.f);
    float xc = fminf(fmaxf(x, 0.f), 255.f);
    float y0 = floorf(yc), x0 = floorf(xc);
    int iy0 = (int)y0, ix0 = (int)x0;
    int iy1 = min(iy0 + 1, 255), ix1 = min(ix0 + 1, 255);
    float wy = yc - y0, wx = xc - x0;
    float v00 = img[iy0 * 256 + ix0];
    float v01 = img[iy0 * 256 + ix1];
    float v10 = img[iy1 * 256 + ix0];
    float v11 = img[iy1 * 256 + ix1];
    return v00 * (1.f - wy) * (1.f - wx) + v01 * (1.f - wy) * wx
         + v10 * wy * (1.f - wx) + v11 * wy * wx;
}

__device__ __forceinline__ float trilin(const float* __restrict__ m3, float y, float x,
                                        float m, float vmin, float vmax, bool cyclic) {
    float c = (m - vmin) / (vmax - vmin) * 32.f - 0.5f;
    int i0, i1; float cw;
    if (cyclic) {
        c = c - floorf(c * (1.f / 32.f)) * 32.f;   // mod 32
        float c0 = floorf(c);
        cw = c - c0;
        i0 = ((int)c0) & 31;
        i1 = (i0 + 1) & 31;
    } else {
        c = fminf(fmaxf(c, 0.f), 31.f);
        float c0 = floorf(c);
        cw = c - c0;
        i0 = (int)c0;
        i1 = min(i0 + 1, 31);
    }
    return (1.f - cw) * bilin(m3 + i0 * 65536, y, x) + cw * bilin(m3 + i1 * 65536, y, x);
}

// Dense evaluation of one queued candidate index (this tile's shared arrays).
__device__ __forceinline__ void dense_eval(
    int ss, const float2* __restrict__ sYX, const float2* __restrict__ sRA,
    const float4* __restrict__ sP2,
    float yi, float xi, float rib, float ai,
    float cai, float sai, float ihw, float ihl,
    float& omax, float& amin)
{
    float2 yx = sYX[ss];
    float2 ra = sRA[ss];
    float dy = yi - yx.x;
    float dx = xi - yx.y;
    float d2 = fmaf(dy, dy, dx * dx);   // > 0 guaranteed by coarse gate

    if (d2 < 1024.f) {                  // align: dist < 32 (strict)
        float ad = ai - ra.y;           // both in [0, pi)
        if (ad < 0.f) ad += PI_F;       // mod pi
        ad = fminf(ad, PI_F - ad);
        float al = fminf(fmaxf(fmaf(ad, 4.f / PI_F, -1.f), -1.f), 1.f);
        amin = fminf(amin, al);
    }

    float rsum = rib + ra.x;
    if (d2 < rsum * rsum) {             // refined overlap gate
        float d2c  = fmaxf(d2, 1e-12f);
        float rinv = rsqrtf(d2c);
        float dist = d2c * rinv;
        float ct = dy * rinv;           // cos(theta)
        float st = dx * rinv;           // sin(theta)
        float4 c2 = sP2[ss];
        float ci = fabsf(fmaf(ct, cai,  st * sai)) + 1e-8f;
        float si = fabsf(fmaf(st, cai, -(ct * sai))) + 1e-8f;
        float cj = fabsf(fmaf(ct, c2.x,  st * c2.y)) + 1e-8f;
        float sj = fabsf(fmaf(st, c2.x, -(ct * c2.y))) + 1e-8f;
        float ti = pow10f(ci * ihw)  + pow10f(si * ihl);
        float tj = pow10f(cj * c2.z) + pow10f(sj * c2.w);
        float ri = powm01f(ti);
        float rj = powm01f(tj);
        float ov = 1.f - __fdividef(dist, ri + rj + 1e-8f);
        omax = fmaxf(omax, fminf(fmaxf(ov, 0.f), 1.f));
    }
}

__global__ __launch_bounds__(256) void pair_kernel(
    const float* __restrict__ cc,
    const float* __restrict__ pem, const float* __restrict__ mwm,
    const float* __restrict__ mlm, const float* __restrict__ mam,
    const float* __restrict__ comb_w, const float* __restrict__ comb_b,
    float* __restrict__ out, int P, int out_size)
{
    __shared__ float2 sYX[TJ];
    __shared__ float2 sRA[TJ];
    __shared__ float4 sP2[TJ];
    __shared__ int    sQ[WPB][QCAP];

    const int bpb  = P / WPB;
    const int b    = blockIdx.x / bpb;
    const int wid  = threadIdx.x >> 5;
    const int i    = (blockIdx.x % bpb) * WPB + wid;
    const int lane = threadIdx.x & 31;
    const unsigned laneLT = (1u << lane) - 1u;
    const int gi   = b * NJ + i;

    float2 yx1 = g_YX[gi];
    float2 ra1 = g_RA[gi];
    float4 p2  = g_P2[gi];
    const bool  pmv = (yx1.x < 1e8f);
    const float yi = yx1.x, xi = yx1.y, rib = ra1.x, ai = ra1.y;
    const float cai = p2.x, sai = p2.y, ihw = p2.z, ihl = p2.w;

    // per-warp-constant coarse radius^2: covers overlap (rb_j <= RBMAX) and align (32^2)
    float cr = rib + RBMAX;
    const float coarse2 = fmaxf(cr * cr, 1024.f);

    float omax = 0.f;   // overlap contributions are >= 0; self/invalid give 0
    float amin = 0.f;   // align matrix always contains 0 entries (self pair)
    int   qn   = 0;     // per-warp candidate-stack depth (warp-uniform)

    for (int tile = 0; tile < NJ; tile += TJ) {
        __syncthreads();
        const float2* __restrict__ gy = g_YX + b * NJ + tile;
        const float2* __restrict__ gr = g_RA + b * NJ + tile;
        const float4* __restrict__ g2 = g_P2 + b * NJ + tile;
        for (int t = threadIdx.x; t < TJ; t += 256) {
            sYX[t] = gy[t];
            sRA[t] = gr[t];
            sP2[t] = g2[t];
        }
        __syncthreads();

        if (pmv) {   // warp-uniform; barriers are outside this branch
            #pragma unroll 4
            for (int s = lane; s < TJ; s += 32) {
                float2 q = sYX[s];
                float dy = yi - q.x;
                float dx = xi - q.y;
                float d2 = fmaf(dy, dy, dx * dx);
                bool cand = (d2 > 0.f) && (d2 < coarse2);

                unsigned m = __ballot_sync(0xffffffffu, cand);
                if (cand) sQ[wid][qn + __popc(m & laneLT)] = s;
                qn += __popc(m);
                if (qn >= 32) {
                    qn -= 32;
                    int ss = sQ[wid][qn + lane];
                    dense_eval(ss, sYX, sRA, sP2, yi, xi, rib, ai,
                               cai, sai, ihw, ihl, omax, amin);
                }
            }
            // tile-end drain (indices reference this tile's shared arrays)
            if (lane < qn) {
                int ss = sQ[wid][lane];
                dense_eval(ss, sYX, sRA, sP2, yi, xi, rib, ai,
                           cai, sai, ihw, ihl, omax, amin);
            }
            qn = 0;
        }
    }

    // warp reductions (one warp == one point)
    #pragma unroll
    for (int off = 16; off; off >>= 1) {
        omax = fmaxf(omax, __shfl_xor_sync(0xffffffffu, omax, off));
        amin = fminf(amin, __shfl_xor_sync(0xffffffffu, amin, off));
    }

    if (lane == 0) {
        int oidx = b * P + i;
        if (oidx < out_size) {
            float e = 0.f;
            if (pmv) {
                const float* pr = cc + (long)gi * 5;
                float y  = fminf(fmaxf(pr[0], 0.f), 256.f);
                float x  = fminf(fmaxf(pr[1], 0.f), 256.f);
                float wv = fminf(fmaxf(pr[2], 2.f), 32.f);
                float lv = fminf(fmaxf(pr[3], 2.f), 32.f);
                float a  = pr[4];
                a = a - floorf(a / PI_F) * PI_F;
                float pos  = bilin(pem, y, x);
                float wen  = trilin(mwm, y, x, wv, 2.f, 32.f, false);
                float len  = trilin(mlm, y, x, lv, 2.f, 32.f, false);
                float aen  = trilin(mam, y, x, a,  0.f, PI_F, true);
                float area = 1.f - 2.f * fminf(fmaxf(wv * lv * (1.f / 256.f), 0.f), 1.f);
                e = pos  * comb_w[0] + wen  * comb_w[1] + len  * comb_w[2]
                  + aen  * comb_w[3] + omax * comb_w[4] + amin * comb_w[5]
                  + area * comb_w[6] + comb_b[0];
            }
            out[oidx] = e;
        }
    }
}

__global__ void reduce_kernel(const float* __restrict__ en, float* __restrict__ outp, int P) {
    __shared__ double sh[256];
    double tot = 0.0;
    for (int b = 0; b < BB; b++) {
        double s = 0.0;
        for (int t = threadIdx.x; t < P; t += 256) s += (double)en[b * P + t];
        sh[threadIdx.x] = s;
        __syncthreads();
        for (int off = 128; off; off >>= 1) {
            if (threadIdx.x < off) sh[threadIdx.x] += sh[threadIdx.x + off];
            __syncthreads();
        }
        if (threadIdx.x == 0) {
            outp[b] = (float)sh[0];
            tot += sh[0];
        }
        __syncthreads();
    }
    if (threadIdx.x == 0) outp[BB] = (float)tot;
}

extern "C" void kernel_launch(void* const* d_in, const int* in_sizes, int n_in,
                              void* d_out, int out_size) {
    const float* cc  = (const float*)d_in[0];
    const int*   msk = (const int*)  d_in[1];
    const float* pem = (const float*)d_in[2];
    const float* mwm = (const float*)d_in[3];
    const float* mlm = (const float*)d_in[4];
    const float* mam = (const float*)d_in[5];
    const float* cwv = (const float*)d_in[6];
    const float* cbv = (const float*)d_in[7];
    float* out = (float*)d_out;

    // compute_context=0 -> P=1024 points/batch (out: 4096 energies + 4 per_subset + 1 total).
    // If out_size indicates the context path (pts == full 9N), use P=9216.
    int P = (out_size >= BB * NJ) ? NJ : 1024;

    prep_kernel<<<(BB * NJ + 255) / 256, 256>>>(cc, msk);
    pair_kernel<<<BB * (P / WPB), 256>>>(cc, pem, mwm, mlm, mam, cwv, cbv, out, P, out_size);
    if (out_size >= BB * P + BB + 1)
        reduce_kernel<<<1, 256>>>(out, out + BB * P, P);
}

// round 9
// speedup vs baseline: 2.2750x; 1.1903x over previous
#include <cuda_runtime.h>
#include <math.h>

#define PI_F 3.14159265358979323846f
#define BB 4
#define NJ 9216
#define WPB 8     // warps (points) per block
#define QCAP 64   // per-warp candidate stack
#define RBMAX 21.12f        // global bound on rb = 1.3195*max(hw,hl)+1e-3, hw,hl<=16
#define NC6 6
#define NCELLS 36
#define CSZ_INV (1.0f / 43.0f)   // cell size 43 > max coarse radius 42.24

// Unsorted per-point data (i-side lookup), preprocessed per launch.
__device__ float2 g_YX[BB * NJ];   // (y,x); invalid -> (1e9,1e9)
__device__ float2 g_RA[BB * NJ];   // (r_bound, angle)
__device__ float4 g_P2[BB * NJ];   // (cos a, sin a, 1/hw, 1/hl)
__device__ int    g_cell[BB * NJ]; // cell id or -1 if invalid

// Binning structures (valid points only, sorted by cell)
__device__ int    g_cnt[BB][NCELLS];
__device__ int    g_off[BB][NCELLS];
__device__ int    g_startA[BB][NCELLS + 1];
__device__ float2 g_sYX[BB * NJ];
__device__ float2 g_sRA[BB * NJ];
__device__ float4 g_sP2[BB * NJ];

__device__ __forceinline__ float pow10f(float x) {
    float x2 = x * x;
    float x4 = x2 * x2;
    float x8 = x4 * x4;
    return x8 * x2;
}

// t^(-0.1) via MUFU lg2/ex2
__device__ __forceinline__ float powm01f(float t) {
    float l, r;
    asm("lg2.approx.f32 %0, %1;" : "=f"(l) : "f"(t));
    l = -0.1f * l;
    asm("ex2.approx.f32 %0, %1;" : "=f"(r) : "f"(l));
    return r;
}

__global__ void zero_kernel() {
    int t = blockIdx.x * blockDim.x + threadIdx.x;
    if (t < BB * NCELLS) {
        ((int*)g_cnt)[t] = 0;
        ((int*)g_off)[t] = 0;
    }
}

__global__ void prep_kernel(const float* __restrict__ cc, const int* __restrict__ mask) {
    int idx = blockIdx.x * blockDim.x + threadIdx.x;
    if (idx >= BB * NJ) return;
    const float* p = cc + (long)idx * 5;
    bool valid = (mask[idx] != 0);
    float y  = fminf(fmaxf(p[0], 0.f), 256.f);
    float x  = fminf(fmaxf(p[1], 0.f), 256.f);
    float wv = fminf(fmaxf(p[2], 2.f), 32.f);
    float lv = fminf(fmaxf(p[3], 2.f), 32.f);
    float a  = p[4];
    a = a - floorf(a / PI_F) * PI_F;          // jnp.mod(a, pi)
    float sa, ca;
    sincosf(a, &sa, &ca);
    float hw = 0.5f * wv, hl = 0.5f * lv;
    // superellipse p=10 radius bound: r <= 2^(1/2 - 1/10) * max(hw,hl)
    float rb = 1.3195080f * fmaxf(hw, hl) + 1e-3f;
    g_YX[idx] = valid ? make_float2(y, x) : make_float2(1e9f, 1e9f);
    g_RA[idx] = make_float2(rb, a);
    g_P2[idx] = make_float4(ca, sa, 1.f / hw, 1.f / hl);
    int cellid = -1;
    if (valid) {
        int cy = min((int)(y * CSZ_INV), NC6 - 1);
        int cx = min((int)(x * CSZ_INV), NC6 - 1);
        cellid = cy * NC6 + cx;
        atomicAdd(&g_cnt[idx / NJ][cellid], 1);
    }
    g_cell[idx] = cellid;
}

__global__ void prefix_kernel() {
    int b = threadIdx.x;
    if (b < BB) {
        int acc = 0;
        for (int c = 0; c < NCELLS; c++) {
            g_startA[b][c] = acc;
            acc += g_cnt[b][c];
        }
        g_startA[b][NCELLS] = acc;
    }
}

__global__ void scatter_kernel() {
    int idx = blockIdx.x * blockDim.x + threadIdx.x;
    if (idx >= BB * NJ) return;
    int cellid = g_cell[idx];
    if (cellid < 0) return;
    int b = idx / NJ;
    int slot = g_startA[b][cellid] + atomicAdd(&g_off[b][cellid], 1);
    int gs = b * NJ + slot;
    g_sYX[gs] = g_YX[idx];
    g_sRA[gs] = g_RA[idx];
    g_sP2[gs] = g_P2[idx];
}

__device__ __forceinline__ float bilin(const float* __restrict__ img, float y, float x) {
    float yc = fminf(fmaxf(y, 0.f), 255.f);
    float xc = fminf(fmaxf(x, 0.f), 255.f);
    float y0 = floorf(yc), x0 = floorf(xc);
    int iy0 = (int)y0, ix0 = (int)x0;
    int iy1 = min(iy0 + 1, 255), ix1 = min(ix0 + 1, 255);
    float wy = yc - y0, wx = xc - x0;
    float v00 = img[iy0 * 256 + ix0];
    float v01 = img[iy0 * 256 + ix1];
    float v10 = img[iy1 * 256 + ix0];
    float v11 = img[iy1 * 256 + ix1];
    return v00 * (1.f - wy) * (1.f - wx) + v01 * (1.f - wy) * wx
         + v10 * wy * (1.f - wx) + v11 * wy * wx;
}

__device__ __forceinline__ float trilin(const float* __restrict__ m3, float y, float x,
                                        float m, float vmin, float vmax, bool cyclic) {
    float c = (m - vmin) / (vmax - vmin) * 32.f - 0.5f;
    int i0, i1; float cw;
    if (cyclic) {
        c = c - floorf(c * (1.f / 32.f)) * 32.f;   // mod 32
        float c0 = floorf(c);
        cw = c - c0;
        i0 = ((int)c0) & 31;
        i1 = (i0 + 1) & 31;
    } else {
        c = fminf(fmaxf(c, 0.f), 31.f);
        float c0 = floorf(c);
        cw = c - c0;
        i0 = (int)c0;
        i1 = min(i0 + 1, 31);
    }
    return (1.f - cw) * bilin(m3 + i0 * 65536, y, x) + cw * bilin(m3 + i1 * 65536, y, x);
}

// Dense evaluation of one queued candidate (global sorted index gs).
__device__ __forceinline__ void dense_eval(
    int gs, float yi, float xi, float rib, float ai,
    float cai, float sai, float ihw, float ihl,
    float& omax, float& amin)
{
    float2 yx = g_sYX[gs];
    float2 ra = g_sRA[gs];
    float dy = yi - yx.x;
    float dx = xi - yx.y;
    float d2 = fmaf(dy, dy, dx * dx);   // > 0 guaranteed by coarse gate

    if (d2 < 1024.f) {                  // align: dist < 32 (strict)
        float ad = ai - ra.y;           // both in [0, pi)
        if (ad < 0.f) ad += PI_F;       // mod pi
        ad = fminf(ad, PI_F - ad);
        float al = fminf(fmaxf(fmaf(ad, 4.f / PI_F, -1.f), -1.f), 1.f);
        amin = fminf(amin, al);
    }

    float rsum = rib + ra.x;
    if (d2 < rsum * rsum) {             // refined overlap gate
        float d2c  = fmaxf(d2, 1e-12f);
        float rinv = rsqrtf(d2c);
        float dist = d2c * rinv;
        float ct = dy * rinv;           // cos(theta)
        float st = dx * rinv;           // sin(theta)
        float4 c2 = g_sP2[gs];
        float ci = fabsf(fmaf(ct, cai,  st * sai)) + 1e-8f;
        float si = fabsf(fmaf(st, cai, -(ct * sai))) + 1e-8f;
        float cj = fabsf(fmaf(ct, c2.x,  st * c2.y)) + 1e-8f;
        float sj = fabsf(fmaf(st, c2.x, -(ct * c2.y))) + 1e-8f;
        float ti = pow10f(ci * ihw)  + pow10f(si * ihl);
        float tj = pow10f(cj * c2.z) + pow10f(sj * c2.w);
        float ri = powm01f(ti);
        float rj = powm01f(tj);
        float ov = 1.f - __fdividef(dist, ri + rj + 1e-8f);
        omax = fmaxf(omax, fminf(fmaxf(ov, 0.f), 1.f));
    }
}

__global__ __launch_bounds__(256) void pair_kernel(
    const float* __restrict__ cc,
    const float* __restrict__ pem, const float* __restrict__ mwm,
    const float* __restrict__ mlm, const float* __restrict__ mam,
    const float* __restrict__ comb_w, const float* __restrict__ comb_b,
    float* __restrict__ out, int P, int out_size)
{
    __shared__ int sQ[WPB][QCAP];

    const int bpb  = P / WPB;
    const int b    = blockIdx.x / bpb;
    const int wid  = threadIdx.x >> 5;
    const int i    = (blockIdx.x % bpb) * WPB + wid;
    const int lane = threadIdx.x & 31;
    const unsigned laneLT = (1u << lane) - 1u;
    const int gi   = b * NJ + i;

    float2 yx1 = g_YX[gi];
    float2 ra1 = g_RA[gi];
    float4 p2  = g_P2[gi];
    const bool  pmv = (yx1.x < 1e8f);
    const float yi = yx1.x, xi = yx1.y, rib = ra1.x, ai = ra1.y;
    const float cai = p2.x, sai = p2.y, ihw = p2.z, ihl = p2.w;

    // per-warp-constant coarse radius^2: covers overlap (rb_j <= RBMAX) and align (32^2)
    float cr = rib + RBMAX;
    const float coarse2 = fmaxf(cr * cr, 1024.f);

    float omax = 0.f;   // overlap contributions are >= 0; self/invalid give 0
    float amin = 0.f;   // align matrix always contains 0 entries (self pair)
    int   qn   = 0;     // per-warp candidate-stack depth (warp-uniform)

    if (pmv) {
        int cy = min((int)(yi * CSZ_INV), NC6 - 1);
        int cx = min((int)(xi * CSZ_INV), NC6 - 1);
        int r0 = max(cy - 1, 0), r1 = min(cy + 1, NC6 - 1);
        int c0 = max(cx - 1, 0), c1 = min(cx + 1, NC6 - 1);

        for (int row = r0; row <= r1; row++) {
            // cells row*6+c0 .. row*6+c1 are contiguous -> single range
            int lo = g_startA[b][row * NC6 + c0];
            int hi = g_startA[b][row * NC6 + c1 + 1];
            for (int base = lo; base < hi; base += 32) {
                int s = base + lane;
                int sc = min(s, hi - 1);              // clamp load, gate with (s<hi)
                float2 q = g_sYX[b * NJ + sc];
                float dy = yi - q.x;
                float dx = xi - q.y;
                float d2 = fmaf(dy, dy, dx * dx);
                bool cand = (s < hi) && (d2 > 0.f) && (d2 < coarse2);

                unsigned m = __ballot_sync(0xffffffffu, cand);
                if (cand) sQ[wid][qn + __popc(m & laneLT)] = sc;
                qn += __popc(m);
                if (qn >= 32) {
                    qn -= 32;
                    int ss = sQ[wid][qn + lane];
                    dense_eval(b * NJ + ss, yi, xi, rib, ai,
                               cai, sai, ihw, ihl, omax, amin);
                }
            }
        }
        // single drain at the end (indices are global sorted, valid throughout)
        if (lane < qn) {
            int ss = sQ[wid][lane];
            dense_eval(b * NJ + ss, yi, xi, rib, ai,
                       cai, sai, ihw, ihl, omax, amin);
        }
    }

    // warp reductions (one warp == one point)
    #pragma unroll
    for (int off = 16; off; off >>= 1) {
        omax = fmaxf(omax, __shfl_xor_sync(0xffffffffu, omax, off));
        amin = fminf(amin, __shfl_xor_sync(0xffffffffu, amin, off));
    }

    if (lane == 0) {
        int oidx = b * P + i;
        if (oidx < out_size) {
            float e = 0.f;
            if (pmv) {
                const float* pr = cc + (long)gi * 5;
                float y  = fminf(fmaxf(pr[0], 0.f), 256.f);
                float x  = fminf(fmaxf(pr[1], 0.f), 256.f);
                float wv = fminf(fmaxf(pr[2], 2.f), 32.f);
                float lv = fminf(fmaxf(pr[3], 2.f), 32.f);
                float a  = pr[4];
                a = a - floorf(a / PI_F) * PI_F;
                float pos  = bilin(pem, y, x);
                float wen  = trilin(mwm, y, x, wv, 2.f, 32.f, false);
                float len  = trilin(mlm, y, x, lv, 2.f, 32.f, false);
                float aen  = trilin(mam, y, x, a,  0.f, PI_F, true);
                float area = 1.f - 2.f * fminf(fmaxf(wv * lv * (1.f / 256.f), 0.f), 1.f);
                e = pos  * comb_w[0] + wen  * comb_w[1] + len  * comb_w[2]
                  + aen  * comb_w[3] + omax * comb_w[4] + amin * comb_w[5]
                  + area * comb_w[6] + comb_b[0];
            }
            out[oidx] = e;
        }
    }
}

__global__ void reduce_kernel(const float* __restrict__ en, float* __restrict__ outp, int P) {
    __shared__ double sh[256];
    double tot = 0.0;
    for (int b = 0; b < BB; b++) {
        double s = 0.0;
        for (int t = threadIdx.x; t < P; t += 256) s += (double)en[b * P + t];
        sh[threadIdx.x] = s;
        __syncthreads();
        for (int off = 128; off; off >>= 1) {
            if (threadIdx.x < off) sh[threadIdx.x] += sh[threadIdx.x + off];
            __syncthreads();
        }
        if (threadIdx.x == 0) {
            outp[b] = (float)sh[0];
            tot += sh[0];
        }
        __syncthreads();
    }
    if (threadIdx.x == 0) outp[BB] = (float)tot;
}

extern "C" void kernel_launch(void* const* d_in, const int* in_sizes, int n_in,
                              void* d_out, int out_size) {
    const float* cc  = (const float*)d_in[0];
    const int*   msk = (const int*)  d_in[1];
    const float* pem = (const float*)d_in[2];
    const float* mwm = (const float*)d_in[3];
    const float* mlm = (const float*)d_in[4];
    const float* mam = (const float*)d_in[5];
    const float* cwv = (const float*)d_in[6];
    const float* cbv = (const float*)d_in[7];
    float* out = (float*)d_out;

    // compute_context=0 -> P=1024 points/batch (out: 4096 energies + 4 per_subset + 1 total).
    // If out_size indicates the context path (pts == full 9N), use P=9216.
    int P = (out_size >= BB * NJ) ? NJ : 1024;

    zero_kernel<<<1, 256>>>();
    prep_kernel<<<(BB * NJ + 255) / 256, 256>>>(cc, msk);
    prefix_kernel<<<1, 32>>>();
    scatter_kernel<<<(BB * NJ + 255) / 256, 256>>>();
    pair_kernel<<<BB * (P / WPB), 256>>>(cc, pem, mwm, mlm, mam, cwv, cbv, out, P, out_size);
    if (out_size >= BB * P + BB + 1)
        reduce_kernel<<<1, 256>>>(out, out + BB * P, P);
}